// round 12
// baseline (speedup 1.0000x reference)
#include <cuda_runtime.h>
#include <cuda_bf16.h>
#include <cstdint>

#define N_ENT  40000
#define NPAD   40064      // 313 * 128
#define D      128
#define BATCH  1024
#define NC     2048       // c rows: 2 branches x 1024
#define MTILES 313
#define NTILES 16
#define NTILE_TOT (MTILES * NTILES)   // 5008
#define GRID_MAIN 296
#define BETA   0.0141421356f          // sqrt(2e-4)
#define PITCH  272        // smem row pitch bytes; 272/16=17 == 1 mod 8 -> ldsm conflict-free

// ---------------- device scratch (static globals: allocation-free) ----------
static __device__ double g_acc;
static __device__ unsigned int g_tile;
static __device__ unsigned int g_done;
static __device__ __align__(16) __nv_bfloat16 g_ebf[(size_t)NPAD * D]; // -beta*ent (pad rows 0)
static __device__ __align__(16) __nv_bfloat16 g_cbf[(size_t)NC * D];   // +beta*c
static __device__ __align__(16) float g_ne4[NPAD];  // |ent_j|^2 * 1e-4 (0 for pads)
static __device__ __align__(16) float g_nb4[NC];    // |c_i|^2   * 1e-4

// ---------------- helpers ---------------------------------------------------
static __device__ __forceinline__ uint32_t smem_u32(const void* p) {
    uint32_t a;
    asm("{ .reg .u64 t; cvta.to.shared.u64 t, %1; cvt.u32.u64 %0, t; }" : "=r"(a) : "l"(p));
    return a;
}
static __device__ __forceinline__ void cp_async16(uint32_t sdst, const void* gsrc) {
    asm volatile("cp.async.cg.shared.global [%0], [%1], 16;" :: "r"(sdst), "l"(gsrc) : "memory");
}
#define CP_COMMIT() asm volatile("cp.async.commit_group;" ::: "memory")
#define CP_WAIT0()  asm volatile("cp.async.wait_group 0;" ::: "memory")

#define LDSM_X4(r0, r1, r2, r3, addr) \
    asm volatile("ldmatrix.sync.aligned.m8n8.x4.shared.b16 {%0,%1,%2,%3}, [%4];" \
        : "=r"(r0), "=r"(r1), "=r"(r2), "=r"(r3) : "r"(addr))
#define LDSM_X4_T(r0, r1, r2, r3, addr) \
    asm volatile("ldmatrix.sync.aligned.m8n8.x4.trans.shared.b16 {%0,%1,%2,%3}, [%4];" \
        : "=r"(r0), "=r"(r1), "=r"(r2), "=r"(r3) : "r"(addr))

static __device__ __forceinline__ void mma16816(float* c, const uint32_t* a,
                                                uint32_t b0, uint32_t b1) {
    asm volatile("mma.sync.aligned.m16n8k16.row.col.f32.bf16.bf16.f32 "
        "{%0,%1,%2,%3}, {%4,%5,%6,%7}, {%8,%9}, {%0,%1,%2,%3};"
        : "+f"(c[0]), "+f"(c[1]), "+f"(c[2]), "+f"(c[3])
        : "r"(a[0]), "r"(a[1]), "r"(a[2]), "r"(a[3]), "r"(b0), "r"(b1));
}
static __device__ __forceinline__ uint32_t pack_bf16(float x, float y) {
    __nv_bfloat162 p = __float22bfloat162_rn(make_float2(x, y));
    return *reinterpret_cast<uint32_t*>(&p);
}

// ---------------------------------------------------------------------------
// Prep: 4 rows per warp (8 lanes/row, 4 independent LDG.128 per thread).
// ent -> -beta*ent bf16 (pad rows 0), c = ent[h]+rseq -> +beta*c bf16,
// fp32 norms * 1e-4. Resets queue/accumulator (graph replays).
// ---------------------------------------------------------------------------
__global__ __launch_bounds__(256) void prep_kernel(
        const float* __restrict__ ent,
        const int* __restrict__ pos_h, const int* __restrict__ neg_h,
        const float* __restrict__ rpos, const float* __restrict__ rneg) {
    const int lane = threadIdx.x & 31;
    const int warp = blockIdx.x * 8 + (threadIdx.x >> 5);
    const int sub  = lane & 7;
    const int row  = warp * 4 + (lane >> 3);
    if (blockIdx.x == 0 && threadIdx.x == 0) {
        g_acc = 0.0; g_tile = GRID_MAIN; g_done = 0;
    }
    const float4* ent4 = reinterpret_cast<const float4*>(ent);

    if (row < NPAD) {
        const bool val = row < N_ENT;
        float4 v[4];
        #pragma unroll
        for (int k = 0; k < 4; ++k)
            v[k] = val ? ent4[(size_t)row * 32 + sub * 4 + k]
                       : make_float4(0.f, 0.f, 0.f, 0.f);
        float s = 0.f;
        #pragma unroll
        for (int k = 0; k < 4; ++k)
            s += v[k].x * v[k].x + v[k].y * v[k].y + v[k].z * v[k].z + v[k].w * v[k].w;
        #pragma unroll
        for (int o = 4; o > 0; o >>= 1) s += __shfl_xor_sync(0xffffffffu, s, o);
        if (sub == 0) g_ne4[row] = s * 1e-4f;

        uint4* dp = reinterpret_cast<uint4*>(g_ebf + (size_t)row * D + sub * 16);
        dp[0] = make_uint4(pack_bf16(-BETA * v[0].x, -BETA * v[0].y),
                           pack_bf16(-BETA * v[0].z, -BETA * v[0].w),
                           pack_bf16(-BETA * v[1].x, -BETA * v[1].y),
                           pack_bf16(-BETA * v[1].z, -BETA * v[1].w));
        dp[1] = make_uint4(pack_bf16(-BETA * v[2].x, -BETA * v[2].y),
                           pack_bf16(-BETA * v[2].z, -BETA * v[2].w),
                           pack_bf16(-BETA * v[3].x, -BETA * v[3].y),
                           pack_bf16(-BETA * v[3].z, -BETA * v[3].w));
    } else if (row < NPAD + NC) {
        const int i  = row - NPAD;
        const int br = i >> 10, bi = i & 1023;
        const int h  = br ? neg_h[bi] : pos_h[bi];
        const float4* rr = reinterpret_cast<const float4*>(br ? rneg : rpos);
        float4 v[4];
        #pragma unroll
        for (int k = 0; k < 4; ++k) {
            float4 e = ent4[(size_t)h * 32 + sub * 4 + k];
            float4 q = rr[(size_t)bi * 32 + sub * 4 + k];
            v[k] = make_float4(e.x + q.x, e.y + q.y, e.z + q.z, e.w + q.w);
        }
        float s = 0.f;
        #pragma unroll
        for (int k = 0; k < 4; ++k)
            s += v[k].x * v[k].x + v[k].y * v[k].y + v[k].z * v[k].z + v[k].w * v[k].w;
        #pragma unroll
        for (int o = 4; o > 0; o >>= 1) s += __shfl_xor_sync(0xffffffffu, s, o);
        if (sub == 0) g_nb4[i] = s * 1e-4f;

        uint4* dp = reinterpret_cast<uint4*>(g_cbf + (size_t)i * D + sub * 16);
        dp[0] = make_uint4(pack_bf16(BETA * v[0].x, BETA * v[0].y),
                           pack_bf16(BETA * v[0].z, BETA * v[0].w),
                           pack_bf16(BETA * v[1].x, BETA * v[1].y),
                           pack_bf16(BETA * v[1].z, BETA * v[1].w));
        dp[1] = make_uint4(pack_bf16(BETA * v[2].x, BETA * v[2].y),
                           pack_bf16(BETA * v[2].z, BETA * v[2].w),
                           pack_bf16(BETA * v[3].x, BETA * v[3].y),
                           pack_bf16(BETA * v[3].z, BETA * v[3].w));
    }
}

// ---------------------------------------------------------------------------
// Diagonal correction (proven r10 version): replaces main's off-diag term
// with the true diagonal term for the 1024 positive pairs.
// ---------------------------------------------------------------------------
__global__ __launch_bounds__(256) void corr_kernel(const int* __restrict__ pos_t) {
    __shared__ double s_c[8];
    const int wid  = threadIdx.x >> 5;
    const int lane = threadIdx.x & 31;
    const int i    = blockIdx.x * 8 + wid;     // 0..1023
    const int t    = pos_t[i];

    const uint2 ua = reinterpret_cast<const uint2*>(g_ebf + (size_t)t * D)[lane];
    const uint2 ub = reinterpret_cast<const uint2*>(g_cbf + (size_t)i * D)[lane];
    float2 a0 = __bfloat1622float2(*reinterpret_cast<const __nv_bfloat162*>(&ua.x));
    float2 a1 = __bfloat1622float2(*reinterpret_cast<const __nv_bfloat162*>(&ua.y));
    float2 b0 = __bfloat1622float2(*reinterpret_cast<const __nv_bfloat162*>(&ub.x));
    float2 b1 = __bfloat1622float2(*reinterpret_cast<const __nv_bfloat162*>(&ub.y));
    float s = a0.x * b0.x + a0.y * b0.y + a1.x * b1.x + a1.y * b1.y;
    #pragma unroll
    for (int o = 16; o > 0; o >>= 1) s += __shfl_xor_sync(0xffffffffu, s, o);

    if (lane == 0) {
        float sq4 = s + g_ne4[t] + g_nb4[i];          // 1e-4 * dist^2
        float u   = rsqrtf(sq4);                      // = 100/dist
        float ex  = exp2f(-1.442695041f * u);
        float off = -fminf(u + ex, 16.118095651f);    // what main contributed
        float dia = fminf(-ex, -1.00000005e-7f);      // true diagonal log(pred)
        s_c[wid] = (double)(dia - off);
    }
    __syncthreads();
    if (threadIdx.x == 0) {
        double tt = 0.0;
        #pragma unroll
        for (int w = 0; w < 8; ++w) tt += s_c[w];
        atomicAdd(&g_acc, tt);
    }
}

// ---------------------------------------------------------------------------
// Persistent main kernel (r10 data path + linear pitch + cross-tile accum):
// 128x128x128 HMMA tiles, atomic queue, in-place prefetch under epilogue,
// norms via double-buffered smem, single reduction/atomic per CTA at the end.
// ---------------------------------------------------------------------------
#define SM_A     0
#define SM_B     34816     // 128 * 272
#define SM_NE    69632     // 2 x 128 f (double buffered)
#define SM_NA    70656     // 2 x 128 f
#define SM_RED   71680     // 8 f
#define SM_CTR   71712     // 1 u32
#define SM_BYTES 71744

static __device__ __forceinline__ void prefetch_tile(uint32_t sb, int tid, int buf,
                                                     int mG, int nG) {
    #pragma unroll
    for (int it = 0; it < 8; ++it) {
        int idx = it * 256 + tid;
        int row = idx >> 4, cc = idx & 15;
        cp_async16(sb + SM_A + row * PITCH + cc * 16, g_ebf + (size_t)(mG + row) * D + cc * 8);
        cp_async16(sb + SM_B + row * PITCH + cc * 16, g_cbf + (size_t)(nG + row) * D + cc * 8);
    }
    if (tid < 32) {
        cp_async16(sb + SM_NE + buf * 512 + tid * 16, g_ne4 + mG + tid * 4);
    } else if (tid < 64) {
        int l = tid - 32;
        cp_async16(sb + SM_NA + buf * 512 + l * 16, g_nb4 + nG + l * 4);
    }
    CP_COMMIT();
}

__global__ __launch_bounds__(256, 2) void loss_main_kernel(float* __restrict__ out) {
    extern __shared__ __align__(16) uint8_t smem[];
    const uint32_t sb = smem_u32(smem);
    float* s_red = reinterpret_cast<float*>(smem + SM_RED);
    unsigned int* s_ctr = reinterpret_cast<unsigned int*>(smem + SM_CTR);

    const int tid  = threadIdx.x;
    const int wid  = tid >> 5;
    const int lane = tid & 31;
    const int wm   = wid >> 1;            // 0..3  (32-row M strip)
    const int wn   = wid & 1;             // 0..1  (64-col N strip)

    // hoisted ldsm base addresses (linear pitch; +32B per k-step)
    uint32_t baseA[2], baseB[4];
    {
        int ra = wm * 32 + (lane & 15);
        baseA[0] = sb + SM_A + (uint32_t)ra * PITCH + (uint32_t)((lane >> 4) << 4);
        baseA[1] = baseA[0] + 16 * PITCH;
        int rb = wn * 64 + (lane & 7) + ((lane >> 4) << 3);
        baseB[0] = sb + SM_B + (uint32_t)rb * PITCH + (uint32_t)(((lane >> 3) & 1) << 4);
        #pragma unroll
        for (int j = 1; j < 4; ++j) baseB[j] = baseB[0] + j * 16 * PITCH;
    }

    unsigned int cur = blockIdx.x;
    int buf = 0;
    int mG = (int)(cur % MTILES) * 128;
    prefetch_tile(sb, tid, buf, mG, (int)(cur / MTILES) * 128);

    float accL = 0.f;                     // cross-tile accumulator
    const int r0l = wm * 32 + (lane >> 2);
    const int c0l = wn * 64 + 2 * (lane & 3);

    for (;;) {
        if (tid == 0) *s_ctr = atomicAdd(&g_tile, 1u);
        CP_WAIT0();
        __syncthreads();                  // tile + norms + s_ctr visible

        float acc[2][8][4];
        #pragma unroll
        for (int mt = 0; mt < 2; ++mt)
            #pragma unroll
            for (int jn = 0; jn < 8; ++jn)
                #pragma unroll
                for (int e = 0; e < 4; ++e) acc[mt][jn][e] = 0.f;

        #pragma unroll
        for (int ks = 0; ks < 8; ++ks) {
            uint32_t a[2][4], b[4][4];
            #pragma unroll
            for (int mt = 0; mt < 2; ++mt)
                LDSM_X4(a[mt][0], a[mt][1], a[mt][2], a[mt][3], baseA[mt] + ks * 32);
            #pragma unroll
            for (int j = 0; j < 4; ++j)
                LDSM_X4_T(b[j][0], b[j][1], b[j][2], b[j][3], baseB[j] + ks * 32);
            #pragma unroll
            for (int mt = 0; mt < 2; ++mt)
                #pragma unroll
                for (int jn = 0; jn < 8; ++jn)
                    mma16816(acc[mt][jn], a[mt], b[jn >> 1][(jn & 1) * 2], b[jn >> 1][(jn & 1) * 2 + 1]);
        }

        unsigned int nxt = *s_ctr;        // written pre-sync by tid0
        __syncthreads();                  // all warps done reading smem tiles

        if (nxt < NTILE_TOT)
            prefetch_tile(sb, tid, buf ^ 1, (int)(nxt % MTILES) * 128,
                                            (int)(nxt / MTILES) * 128);

        // ---- epilogue: sq4 = acc + ne4 + na4 == 1e-4 * dist^2 ----
        const float* sne = reinterpret_cast<const float*>(smem + SM_NE + buf * 512);
        const float* sna = reinterpret_cast<const float*>(smem + SM_NA + buf * 512);

        float ner[4];
        #pragma unroll
        for (int q = 0; q < 4; ++q) ner[q] = sne[r0l + q * 8];   // q = mt*2+half
        float2 nac[8];
        const float2* sna2 = reinterpret_cast<const float2*>(sna);
        #pragma unroll
        for (int jn = 0; jn < 8; ++jn) nac[jn] = sna2[(c0l + jn * 8) >> 1];

        if (mG + 128 <= N_ENT) {          // fast path (312/313 tiles)
            #pragma unroll
            for (int mt = 0; mt < 2; ++mt) {
                #pragma unroll
                for (int half = 0; half < 2; ++half) {
                    const float ne = ner[mt * 2 + half];
                    #pragma unroll
                    for (int jn = 0; jn < 8; ++jn) {
                        float2 na2 = nac[jn];
                        #pragma unroll
                        for (int e = 0; e < 2; ++e) {
                            float sq4 = acc[mt][jn][half * 2 + e] + ne + (e ? na2.y : na2.x);
                            float u   = rsqrtf(sq4);
                            float ex  = exp2f(-1.442695041f * u);
                            accL += fminf(u + ex, 16.118095651f);
                        }
                    }
                }
            }
        } else {                           // boundary tile: pad rows excluded
            #pragma unroll
            for (int mt = 0; mt < 2; ++mt) {
                #pragma unroll
                for (int half = 0; half < 2; ++half) {
                    const bool valid = (mG + r0l + mt * 16 + half * 8) < N_ENT;
                    const float ne = ner[mt * 2 + half];
                    #pragma unroll
                    for (int jn = 0; jn < 8; ++jn) {
                        float2 na2 = nac[jn];
                        #pragma unroll
                        for (int e = 0; e < 2; ++e) {
                            float sq4 = acc[mt][jn][half * 2 + e] + ne + (e ? na2.y : na2.x);
                            float u   = rsqrtf(sq4);
                            float ex  = exp2f(-1.442695041f * u);
                            float m   = fminf(u + ex, 16.118095651f);
                            if (valid) accL += m;
                        }
                    }
                }
            }
        }

        if (nxt >= NTILE_TOT) break;
        buf ^= 1;
        mG = (int)(nxt % MTILES) * 128;
    }

    // ---- once per CTA: reduce + single double atomic ----
    float v = -accL;
    #pragma unroll
    for (int o = 16; o > 0; o >>= 1) v += __shfl_xor_sync(0xffffffffu, v, o);
    if (lane == 0) s_red[wid] = v;
    __syncthreads();
    if (tid == 0) {
        float s = 0.f;
        #pragma unroll
        for (int w = 0; w < 8; ++w) s += s_red[w];
        atomicAdd(&g_acc, (double)s);
        __threadfence();
        unsigned int d = atomicAdd(&g_done, 1u);
        if (d == GRID_MAIN - 1) {
            double a = *((volatile double*)&g_acc);
            out[0] = (float)(-a / ((double)BATCH * (double)N_ENT));
        }
    }
}

extern "C" void kernel_launch(void* const* d_in, const int* in_sizes, int n_in,
                              void* d_out, int out_size) {
    const int*   pos_h = (const int*)d_in[0];
    const int*   pos_t = (const int*)d_in[1];
    const int*   neg_h = (const int*)d_in[2];
    // d_in[3] = neg_t_batch: unused by the reference math.
    const float* rpos  = (const float*)d_in[4];
    const float* rneg  = (const float*)d_in[5];
    const float* ent   = (const float*)d_in[6];
    // d_in[7] = L1_flag: fixed 0 (Euclidean path).

    cudaFuncSetAttribute(loss_main_kernel,
                         cudaFuncAttributeMaxDynamicSharedMemorySize, SM_BYTES);

    prep_kernel<<<1316, 256>>>(ent, pos_h, neg_h, rpos, rneg);   // 1316*8*4 = 42112 rows
    corr_kernel<<<BATCH / 8, 256>>>(pos_t);
    loss_main_kernel<<<GRID_MAIN, 256, SM_BYTES>>>((float*)d_out);
}

// round 13
// speedup vs baseline: 1.2000x; 1.2000x over previous
#include <cuda_runtime.h>
#include <cuda_bf16.h>
#include <cstdint>

#define N_ENT  40000
#define NPAD   40064      // 313 * 128
#define D      128
#define BATCH  1024
#define NC     2048       // c rows: 2 branches x 1024
#define MTILES 313
#define NTILES 32         // 2048 / 64
#define NTILE_TOT (MTILES * NTILES)   // 10016
#define GRID_MAIN 592
#define BETA   0.0141421356f          // sqrt(2e-4)

// ---------------- device scratch (static globals: allocation-free) ----------
static __device__ double g_acc;
static __device__ unsigned int g_tile;
static __device__ unsigned int g_done;
static __device__ __align__(16) __nv_bfloat16 g_ebf[(size_t)NPAD * D]; // -beta*ent (pad rows 0)
static __device__ __align__(16) __nv_bfloat16 g_cbf[(size_t)NC * D];   // +beta*c
static __device__ __align__(16) float g_ne4[NPAD];  // |ent_j|^2 * 1e-4 (0 for pads)
static __device__ __align__(16) float g_nb4[NC];    // |c_i|^2   * 1e-4

// ---------------- helpers ---------------------------------------------------
static __device__ __forceinline__ uint32_t smem_u32(const void* p) {
    uint32_t a;
    asm("{ .reg .u64 t; cvta.to.shared.u64 t, %1; cvt.u32.u64 %0, t; }" : "=r"(a) : "l"(p));
    return a;
}
static __device__ __forceinline__ void cp_async16(uint32_t sdst, const void* gsrc) {
    asm volatile("cp.async.cg.shared.global [%0], [%1], 16;" :: "r"(sdst), "l"(gsrc) : "memory");
}
#define CP_COMMIT() asm volatile("cp.async.commit_group;" ::: "memory")
#define CP_WAIT0()  asm volatile("cp.async.wait_group 0;" ::: "memory")

#define LDSM_X4(r0, r1, r2, r3, addr) \
    asm volatile("ldmatrix.sync.aligned.m8n8.x4.shared.b16 {%0,%1,%2,%3}, [%4];" \
        : "=r"(r0), "=r"(r1), "=r"(r2), "=r"(r3) : "r"(addr))
#define LDSM_X4_T(r0, r1, r2, r3, addr) \
    asm volatile("ldmatrix.sync.aligned.m8n8.x4.trans.shared.b16 {%0,%1,%2,%3}, [%4];" \
        : "=r"(r0), "=r"(r1), "=r"(r2), "=r"(r3) : "r"(addr))

static __device__ __forceinline__ void mma16816(float* c, const uint32_t* a,
                                                uint32_t b0, uint32_t b1) {
    asm volatile("mma.sync.aligned.m16n8k16.row.col.f32.bf16.bf16.f32 "
        "{%0,%1,%2,%3}, {%4,%5,%6,%7}, {%8,%9}, {%0,%1,%2,%3};"
        : "+f"(c[0]), "+f"(c[1]), "+f"(c[2]), "+f"(c[3])
        : "r"(a[0]), "r"(a[1]), "r"(a[2]), "r"(a[3]), "r"(b0), "r"(b1));
}
static __device__ __forceinline__ uint32_t pack_bf16(float x, float y) {
    __nv_bfloat162 p = __float22bfloat162_rn(make_float2(x, y));
    return *reinterpret_cast<uint32_t*>(&p);
}

// ---------------------------------------------------------------------------
// Prep (r12 proven, 8.7us): 4 rows per warp (8 lanes/row, MLP=4).
// ---------------------------------------------------------------------------
__global__ __launch_bounds__(256) void prep_kernel(
        const float* __restrict__ ent,
        const int* __restrict__ pos_h, const int* __restrict__ neg_h,
        const float* __restrict__ rpos, const float* __restrict__ rneg) {
    const int lane = threadIdx.x & 31;
    const int warp = blockIdx.x * 8 + (threadIdx.x >> 5);
    const int sub  = lane & 7;
    const int row  = warp * 4 + (lane >> 3);
    if (blockIdx.x == 0 && threadIdx.x == 0) {
        g_acc = 0.0; g_tile = GRID_MAIN; g_done = 0;
    }
    const float4* ent4 = reinterpret_cast<const float4*>(ent);

    if (row < NPAD) {
        const bool val = row < N_ENT;
        float4 v[4];
        #pragma unroll
        for (int k = 0; k < 4; ++k)
            v[k] = val ? ent4[(size_t)row * 32 + sub * 4 + k]
                       : make_float4(0.f, 0.f, 0.f, 0.f);
        float s = 0.f;
        #pragma unroll
        for (int k = 0; k < 4; ++k)
            s += v[k].x * v[k].x + v[k].y * v[k].y + v[k].z * v[k].z + v[k].w * v[k].w;
        #pragma unroll
        for (int o = 4; o > 0; o >>= 1) s += __shfl_xor_sync(0xffffffffu, s, o);
        if (sub == 0) g_ne4[row] = s * 1e-4f;

        uint4* dp = reinterpret_cast<uint4*>(g_ebf + (size_t)row * D + sub * 16);
        dp[0] = make_uint4(pack_bf16(-BETA * v[0].x, -BETA * v[0].y),
                           pack_bf16(-BETA * v[0].z, -BETA * v[0].w),
                           pack_bf16(-BETA * v[1].x, -BETA * v[1].y),
                           pack_bf16(-BETA * v[1].z, -BETA * v[1].w));
        dp[1] = make_uint4(pack_bf16(-BETA * v[2].x, -BETA * v[2].y),
                           pack_bf16(-BETA * v[2].z, -BETA * v[2].w),
                           pack_bf16(-BETA * v[3].x, -BETA * v[3].y),
                           pack_bf16(-BETA * v[3].z, -BETA * v[3].w));
    } else if (row < NPAD + NC) {
        const int i  = row - NPAD;
        const int br = i >> 10, bi = i & 1023;
        const int h  = br ? neg_h[bi] : pos_h[bi];
        const float4* rr = reinterpret_cast<const float4*>(br ? rneg : rpos);
        float4 v[4];
        #pragma unroll
        for (int k = 0; k < 4; ++k) {
            float4 e = ent4[(size_t)h * 32 + sub * 4 + k];
            float4 q = rr[(size_t)bi * 32 + sub * 4 + k];
            v[k] = make_float4(e.x + q.x, e.y + q.y, e.z + q.z, e.w + q.w);
        }
        float s = 0.f;
        #pragma unroll
        for (int k = 0; k < 4; ++k)
            s += v[k].x * v[k].x + v[k].y * v[k].y + v[k].z * v[k].z + v[k].w * v[k].w;
        #pragma unroll
        for (int o = 4; o > 0; o >>= 1) s += __shfl_xor_sync(0xffffffffu, s, o);
        if (sub == 0) g_nb4[i] = s * 1e-4f;

        uint4* dp = reinterpret_cast<uint4*>(g_cbf + (size_t)i * D + sub * 16);
        dp[0] = make_uint4(pack_bf16(BETA * v[0].x, BETA * v[0].y),
                           pack_bf16(BETA * v[0].z, BETA * v[0].w),
                           pack_bf16(BETA * v[1].x, BETA * v[1].y),
                           pack_bf16(BETA * v[1].z, BETA * v[1].w));
        dp[1] = make_uint4(pack_bf16(BETA * v[2].x, BETA * v[2].y),
                           pack_bf16(BETA * v[2].z, BETA * v[2].w),
                           pack_bf16(BETA * v[3].x, BETA * v[3].y),
                           pack_bf16(BETA * v[3].z, BETA * v[3].w));
    }
}

// ---------------------------------------------------------------------------
// Diagonal correction (proven): swaps main's off-diag term for the true
// diagonal term on the 1024 positive pairs.
// ---------------------------------------------------------------------------
__global__ __launch_bounds__(256) void corr_kernel(const int* __restrict__ pos_t) {
    __shared__ double s_c[8];
    const int wid  = threadIdx.x >> 5;
    const int lane = threadIdx.x & 31;
    const int i    = blockIdx.x * 8 + wid;     // 0..1023
    const int t    = pos_t[i];

    const uint2 ua = reinterpret_cast<const uint2*>(g_ebf + (size_t)t * D)[lane];
    const uint2 ub = reinterpret_cast<const uint2*>(g_cbf + (size_t)i * D)[lane];
    float2 a0 = __bfloat1622float2(*reinterpret_cast<const __nv_bfloat162*>(&ua.x));
    float2 a1 = __bfloat1622float2(*reinterpret_cast<const __nv_bfloat162*>(&ua.y));
    float2 b0 = __bfloat1622float2(*reinterpret_cast<const __nv_bfloat162*>(&ub.x));
    float2 b1 = __bfloat1622float2(*reinterpret_cast<const __nv_bfloat162*>(&ub.y));
    float s = a0.x * b0.x + a0.y * b0.y + a1.x * b1.x + a1.y * b1.y;
    #pragma unroll
    for (int o = 16; o > 0; o >>= 1) s += __shfl_xor_sync(0xffffffffu, s, o);

    if (lane == 0) {
        float sq4 = s + g_ne4[t] + g_nb4[i];          // 1e-4 * dist^2
        float u   = rsqrtf(sq4);                      // = 100/dist
        float ex  = exp2f(-1.442695041f * u);
        float off = -fminf(u + ex, 16.118095651f);    // what main contributed
        float dia = fminf(-ex, -1.00000005e-7f);      // true diagonal log(pred)
        s_c[wid] = (double)(dia - off);
    }
    __syncthreads();
    if (threadIdx.x == 0) {
        double tt = 0.0;
        #pragma unroll
        for (int w = 0; w < 8; ++w) tt += s_c[w];
        atomicAdd(&g_acc, tt);
    }
}

// ---------------------------------------------------------------------------
// Persistent main kernel: 4 CTAs/SM x 128 threads, tile 128(M) x 64(N).
// 4 independent queue-driven streams per SM decorrelate mainloop (tensor)
// and epilogue (MUFU) phases; startup stagger breaks initial lock-step.
// r10-proven XOR-swizzle smem + ldsm/mma path, warp tile 32x64 unchanged.
// ---------------------------------------------------------------------------
#define SM_A     0
#define SM_B     32768     // A: 128 rows * 256B
#define SM_NE    49152     // 2 x 128 f (double buffered)
#define SM_NA    50176     // 2 x 64 f
#define SM_RED   50688     // 4 f
#define SM_CTR   50704     // 1 u32
#define SM_BYTES 50752

static __device__ __forceinline__ void prefetch_tile(uint32_t sb, int tid, int buf,
                                                     int mG, int nG) {
    #pragma unroll
    for (int it = 0; it < 16; ++it) {            // A: 2048 16B chunks
        int idx = it * 128 + tid;
        int row = idx >> 4, cc = idx & 15;
        uint32_t sw = (uint32_t)((cc ^ (row & 7)) << 4);
        cp_async16(sb + SM_A + row * 256 + sw, g_ebf + (size_t)(mG + row) * D + cc * 8);
    }
    #pragma unroll
    for (int it = 0; it < 8; ++it) {             // B: 1024 16B chunks
        int idx = it * 128 + tid;
        int row = idx >> 4, cc = idx & 15;
        uint32_t sw = (uint32_t)((cc ^ (row & 7)) << 4);
        cp_async16(sb + SM_B + row * 256 + sw, g_cbf + (size_t)(nG + row) * D + cc * 8);
    }
    if (tid < 32) {
        cp_async16(sb + SM_NE + buf * 512 + tid * 16, g_ne4 + mG + tid * 4);
    } else if (tid < 48) {
        int l = tid - 32;
        cp_async16(sb + SM_NA + buf * 256 + l * 16, g_nb4 + nG + l * 4);
    }
    CP_COMMIT();
}

__global__ __launch_bounds__(128, 4) void loss_main_kernel(float* __restrict__ out) {
    extern __shared__ __align__(16) uint8_t smem[];
    const uint32_t sb = smem_u32(smem);
    float* s_red = reinterpret_cast<float*>(smem + SM_RED);
    unsigned int* s_ctr = reinterpret_cast<unsigned int*>(smem + SM_CTR);

    const int tid  = threadIdx.x;
    const int wid  = tid >> 5;            // 0..3 = M strip of 32
    const int lane = tid & 31;

    // startup stagger: ~0/1k/2k/3k cyc dependent-FMA delay by CTA parity
    {
        int iters = (blockIdx.x & 3) * 256;
        float d = 1.0f;
        for (int k = 0; k < iters; ++k) d = fmaf(d, 1.0000001f, 1e-30f);
        asm volatile("" :: "f"(d));
    }

    unsigned int cur = blockIdx.x;
    int buf = 0;
    int mG = (int)(cur % MTILES) * 128;
    prefetch_tile(sb, tid, buf, mG, (int)(cur / MTILES) * 64);

    float accL = 0.f;                     // cross-tile accumulator
    const int r0l = wid * 32 + (lane >> 2);
    const int c0l = 2 * (lane & 3);

    for (;;) {
        if (tid == 0) *s_ctr = atomicAdd(&g_tile, 1u);
        CP_WAIT0();
        __syncthreads();                  // tile + norms + s_ctr visible

        float acc[2][8][4];
        #pragma unroll
        for (int mt = 0; mt < 2; ++mt)
            #pragma unroll
            for (int jn = 0; jn < 8; ++jn)
                #pragma unroll
                for (int e = 0; e < 4; ++e) acc[mt][jn][e] = 0.f;

        #pragma unroll
        for (int ks = 0; ks < 8; ++ks) {
            uint32_t a[2][4], b[4][4];
            #pragma unroll
            for (int mt = 0; mt < 2; ++mt) {
                int row = wid * 32 + mt * 16 + (lane & 15);
                int cc  = 2 * ks + (lane >> 4);
                uint32_t ad = sb + SM_A + row * 256 + (uint32_t)((cc ^ (row & 7)) << 4);
                LDSM_X4(a[mt][0], a[mt][1], a[mt][2], a[mt][3], ad);
            }
            #pragma unroll
            for (int j = 0; j < 4; ++j) {
                int row = j * 16 + (lane & 7) + ((lane >> 4) << 3);
                int cc  = 2 * ks + ((lane >> 3) & 1);
                uint32_t bd = sb + SM_B + row * 256 + (uint32_t)((cc ^ (row & 7)) << 4);
                LDSM_X4_T(b[j][0], b[j][1], b[j][2], b[j][3], bd);
            }
            #pragma unroll
            for (int mt = 0; mt < 2; ++mt)
                #pragma unroll
                for (int jn = 0; jn < 8; ++jn)
                    mma16816(acc[mt][jn], a[mt], b[jn >> 1][(jn & 1) * 2], b[jn >> 1][(jn & 1) * 2 + 1]);
        }

        unsigned int nxt = *s_ctr;        // written pre-sync by tid0
        __syncthreads();                  // all warps done reading smem tiles

        if (nxt < NTILE_TOT)
            prefetch_tile(sb, tid, buf ^ 1, (int)(nxt % MTILES) * 128,
                                            (int)(nxt / MTILES) * 64);

        // ---- epilogue: sq4 = acc + ne4 + na4 == 1e-4 * dist^2 ----
        const float* sne = reinterpret_cast<const float*>(smem + SM_NE + buf * 512);
        const float* sna = reinterpret_cast<const float*>(smem + SM_NA + buf * 256);

        float ner[4];
        #pragma unroll
        for (int q = 0; q < 4; ++q) ner[q] = sne[r0l + q * 8];   // q = mt*2+half
        float2 nac[8];
        const float2* sna2 = reinterpret_cast<const float2*>(sna);
        #pragma unroll
        for (int jn = 0; jn < 8; ++jn) nac[jn] = sna2[(c0l + jn * 8) >> 1];

        if (mG + 128 <= N_ENT) {          // fast path (312/313 bands)
            #pragma unroll
            for (int mt = 0; mt < 2; ++mt) {
                #pragma unroll
                for (int half = 0; half < 2; ++half) {
                    const float ne = ner[mt * 2 + half];
                    #pragma unroll
                    for (int jn = 0; jn < 8; ++jn) {
                        float2 na2 = nac[jn];
                        #pragma unroll
                        for (int e = 0; e < 2; ++e) {
                            float sq4 = acc[mt][jn][half * 2 + e] + ne + (e ? na2.y : na2.x);
                            float u   = rsqrtf(sq4);
                            float ex  = exp2f(-1.442695041f * u);
                            accL += fminf(u + ex, 16.118095651f);
                        }
                    }
                }
            }
        } else {                           // boundary band: pad rows excluded
            #pragma unroll
            for (int mt = 0; mt < 2; ++mt) {
                #pragma unroll
                for (int half = 0; half < 2; ++half) {
                    const bool valid = (mG + r0l + mt * 16 + half * 8) < N_ENT;
                    const float ne = ner[mt * 2 + half];
                    #pragma unroll
                    for (int jn = 0; jn < 8; ++jn) {
                        float2 na2 = nac[jn];
                        #pragma unroll
                        for (int e = 0; e < 2; ++e) {
                            float sq4 = acc[mt][jn][half * 2 + e] + ne + (e ? na2.y : na2.x);
                            float u   = rsqrtf(sq4);
                            float ex  = exp2f(-1.442695041f * u);
                            float m   = fminf(u + ex, 16.118095651f);
                            if (valid) accL += m;
                        }
                    }
                }
            }
        }

        if (nxt >= NTILE_TOT) break;
        buf ^= 1;
        mG = (int)(nxt % MTILES) * 128;
    }

    // ---- once per CTA: reduce + single double atomic ----
    float v = -accL;
    #pragma unroll
    for (int o = 16; o > 0; o >>= 1) v += __shfl_xor_sync(0xffffffffu, v, o);
    if (lane == 0) s_red[wid] = v;
    __syncthreads();
    if (tid == 0) {
        float s = s_red[0] + s_red[1] + s_red[2] + s_red[3];
        atomicAdd(&g_acc, (double)s);
        __threadfence();
        unsigned int d = atomicAdd(&g_done, 1u);
        if (d == GRID_MAIN - 1) {
            double a = *((volatile double*)&g_acc);
            out[0] = (float)(-a / ((double)BATCH * (double)N_ENT));
        }
    }
}

extern "C" void kernel_launch(void* const* d_in, const int* in_sizes, int n_in,
                              void* d_out, int out_size) {
    const int*   pos_h = (const int*)d_in[0];
    const int*   pos_t = (const int*)d_in[1];
    const int*   neg_h = (const int*)d_in[2];
    // d_in[3] = neg_t_batch: unused by the reference math.
    const float* rpos  = (const float*)d_in[4];
    const float* rneg  = (const float*)d_in[5];
    const float* ent   = (const float*)d_in[6];
    // d_in[7] = L1_flag: fixed 0 (Euclidean path).

    cudaFuncSetAttribute(loss_main_kernel,
                         cudaFuncAttributeMaxDynamicSharedMemorySize, SM_BYTES);

    prep_kernel<<<1316, 256>>>(ent, pos_h, neg_h, rpos, rneg);   // 1316*8*4 = 42112 rows
    corr_kernel<<<BATCH / 8, 256>>>(pos_t);
    loss_main_kernel<<<GRID_MAIN, 128, SM_BYTES>>>((float*)d_out);
}

// round 14
// speedup vs baseline: 1.2243x; 1.0203x over previous
#include <cuda_runtime.h>
#include <cuda_bf16.h>
#include <cstdint>

#define N_ENT  40000
#define NPAD   40064      // 313 * 128
#define D      128
#define BATCH  1024
#define NC     2048       // c rows: 2 branches x 1024
#define MTILES 313
#define NTILES 32         // 2048 / 64
#define NTILE_TOT (MTILES * NTILES)   // 10016
#define GRID_MAIN 592
// scale so rsqrt(acc+norms) = 144.2695/dist = (100/dist)/ln2
#define NSCALE 4.80453e-5f
#define BETA   9.80258e-3f            // sqrt(2*NSCALE)
#define LN2F   0.69314718f

// ---------------- device scratch (static globals: allocation-free) ----------
static __device__ double g_acc;
static __device__ unsigned int g_tile;
static __device__ unsigned int g_done;
static __device__ __align__(16) __nv_bfloat16 g_ebf[(size_t)NPAD * D]; // -BETA*ent (pad rows 0)
static __device__ __align__(16) __nv_bfloat16 g_cbf[(size_t)NC * D];   // +BETA*c
static __device__ __align__(16) float g_ne4[NPAD];  // |ent_j|^2 * NSCALE (0 for pads)
static __device__ __align__(16) float g_nb4[NC];    // |c_i|^2   * NSCALE

// ---------------- helpers ---------------------------------------------------
static __device__ __forceinline__ uint32_t smem_u32(const void* p) {
    uint32_t a;
    asm("{ .reg .u64 t; cvta.to.shared.u64 t, %1; cvt.u32.u64 %0, t; }" : "=r"(a) : "l"(p));
    return a;
}
static __device__ __forceinline__ void cp_async16(uint32_t sdst, const void* gsrc) {
    asm volatile("cp.async.cg.shared.global [%0], [%1], 16;" :: "r"(sdst), "l"(gsrc) : "memory");
}
#define CP_COMMIT() asm volatile("cp.async.commit_group;" ::: "memory")
#define CP_WAIT0()  asm volatile("cp.async.wait_group 0;" ::: "memory")

#define LDSM_X4(r0, r1, r2, r3, addr) \
    asm volatile("ldmatrix.sync.aligned.m8n8.x4.shared.b16 {%0,%1,%2,%3}, [%4];" \
        : "=r"(r0), "=r"(r1), "=r"(r2), "=r"(r3) : "r"(addr))
#define LDSM_X4_T(r0, r1, r2, r3, addr) \
    asm volatile("ldmatrix.sync.aligned.m8n8.x4.trans.shared.b16 {%0,%1,%2,%3}, [%4];" \
        : "=r"(r0), "=r"(r1), "=r"(r2), "=r"(r3) : "r"(addr))

static __device__ __forceinline__ void mma16816(float* c, const uint32_t* a,
                                                uint32_t b0, uint32_t b1) {
    asm volatile("mma.sync.aligned.m16n8k16.row.col.f32.bf16.bf16.f32 "
        "{%0,%1,%2,%3}, {%4,%5,%6,%7}, {%8,%9}, {%0,%1,%2,%3};"
        : "+f"(c[0]), "+f"(c[1]), "+f"(c[2]), "+f"(c[3])
        : "r"(a[0]), "r"(a[1]), "r"(a[2]), "r"(a[3]), "r"(b0), "r"(b1));
}
static __device__ __forceinline__ uint32_t pack_bf16(float x, float y) {
    __nv_bfloat162 p = __float22bfloat162_rn(make_float2(x, y));
    return *reinterpret_cast<uint32_t*>(&p);
}

// ---------------------------------------------------------------------------
// Prep (proven): 4 rows per warp (8 lanes/row, MLP=4). New scaling constants.
// ---------------------------------------------------------------------------
__global__ __launch_bounds__(256) void prep_kernel(
        const float* __restrict__ ent,
        const int* __restrict__ pos_h, const int* __restrict__ neg_h,
        const float* __restrict__ rpos, const float* __restrict__ rneg) {
    const int lane = threadIdx.x & 31;
    const int warp = blockIdx.x * 8 + (threadIdx.x >> 5);
    const int sub  = lane & 7;
    const int row  = warp * 4 + (lane >> 3);
    if (blockIdx.x == 0 && threadIdx.x == 0) {
        g_acc = 0.0; g_tile = GRID_MAIN; g_done = 0;
    }
    const float4* ent4 = reinterpret_cast<const float4*>(ent);

    if (row < NPAD) {
        const bool val = row < N_ENT;
        float4 v[4];
        #pragma unroll
        for (int k = 0; k < 4; ++k)
            v[k] = val ? ent4[(size_t)row * 32 + sub * 4 + k]
                       : make_float4(0.f, 0.f, 0.f, 0.f);
        float s = 0.f;
        #pragma unroll
        for (int k = 0; k < 4; ++k)
            s += v[k].x * v[k].x + v[k].y * v[k].y + v[k].z * v[k].z + v[k].w * v[k].w;
        #pragma unroll
        for (int o = 4; o > 0; o >>= 1) s += __shfl_xor_sync(0xffffffffu, s, o);
        if (sub == 0) g_ne4[row] = s * NSCALE;

        uint4* dp = reinterpret_cast<uint4*>(g_ebf + (size_t)row * D + sub * 16);
        dp[0] = make_uint4(pack_bf16(-BETA * v[0].x, -BETA * v[0].y),
                           pack_bf16(-BETA * v[0].z, -BETA * v[0].w),
                           pack_bf16(-BETA * v[1].x, -BETA * v[1].y),
                           pack_bf16(-BETA * v[1].z, -BETA * v[1].w));
        dp[1] = make_uint4(pack_bf16(-BETA * v[2].x, -BETA * v[2].y),
                           pack_bf16(-BETA * v[2].z, -BETA * v[2].w),
                           pack_bf16(-BETA * v[3].x, -BETA * v[3].y),
                           pack_bf16(-BETA * v[3].z, -BETA * v[3].w));
    } else if (row < NPAD + NC) {
        const int i  = row - NPAD;
        const int br = i >> 10, bi = i & 1023;
        const int h  = br ? neg_h[bi] : pos_h[bi];
        const float4* rr = reinterpret_cast<const float4*>(br ? rneg : rpos);
        float4 v[4];
        #pragma unroll
        for (int k = 0; k < 4; ++k) {
            float4 e = ent4[(size_t)h * 32 + sub * 4 + k];
            float4 q = rr[(size_t)bi * 32 + sub * 4 + k];
            v[k] = make_float4(e.x + q.x, e.y + q.y, e.z + q.z, e.w + q.w);
        }
        float s = 0.f;
        #pragma unroll
        for (int k = 0; k < 4; ++k)
            s += v[k].x * v[k].x + v[k].y * v[k].y + v[k].z * v[k].z + v[k].w * v[k].w;
        #pragma unroll
        for (int o = 4; o > 0; o >>= 1) s += __shfl_xor_sync(0xffffffffu, s, o);
        if (sub == 0) g_nb4[i] = s * NSCALE;

        uint4* dp = reinterpret_cast<uint4*>(g_cbf + (size_t)i * D + sub * 16);
        dp[0] = make_uint4(pack_bf16(BETA * v[0].x, BETA * v[0].y),
                           pack_bf16(BETA * v[0].z, BETA * v[0].w),
                           pack_bf16(BETA * v[1].x, BETA * v[1].y),
                           pack_bf16(BETA * v[1].z, BETA * v[1].w));
        dp[1] = make_uint4(pack_bf16(BETA * v[2].x, BETA * v[2].y),
                           pack_bf16(BETA * v[2].z, BETA * v[2].w),
                           pack_bf16(BETA * v[3].x, BETA * v[3].y),
                           pack_bf16(BETA * v[3].z, BETA * v[3].w));
    }
}

// ---------------------------------------------------------------------------
// Diagonal correction: swaps main's off-diag term for the true diagonal term
// on the 1024 positive pairs, mirroring main's exact formula.
// ---------------------------------------------------------------------------
__global__ __launch_bounds__(256) void corr_kernel(const int* __restrict__ pos_t) {
    __shared__ double s_c[8];
    const int wid  = threadIdx.x >> 5;
    const int lane = threadIdx.x & 31;
    const int i    = blockIdx.x * 8 + wid;     // 0..1023
    const int t    = pos_t[i];

    const uint2 ua = reinterpret_cast<const uint2*>(g_ebf + (size_t)t * D)[lane];
    const uint2 ub = reinterpret_cast<const uint2*>(g_cbf + (size_t)i * D)[lane];
    float2 a0 = __bfloat1622float2(*reinterpret_cast<const __nv_bfloat162*>(&ua.x));
    float2 a1 = __bfloat1622float2(*reinterpret_cast<const __nv_bfloat162*>(&ua.y));
    float2 b0 = __bfloat1622float2(*reinterpret_cast<const __nv_bfloat162*>(&ub.x));
    float2 b1 = __bfloat1622float2(*reinterpret_cast<const __nv_bfloat162*>(&ub.y));
    float s = a0.x * b0.x + a0.y * b0.y + a1.x * b1.x + a1.y * b1.y;
    #pragma unroll
    for (int o = 16; o > 0; o >>= 1) s += __shfl_xor_sync(0xffffffffu, s, o);

    if (lane == 0) {
        float sq  = s + g_ne4[t] + g_nb4[i];          // (dist/144.2695)^2
        float v   = rsqrtf(sq);                       // 1.4427 * 100/dist
        float ex  = exp2f(-v);                        // e^{-100/dist}
        float off = -(LN2F * v + ex);                 // what main contributed
        float dia = fminf(-ex, -1.00000005e-7f);      // true diagonal log(pred)
        s_c[wid] = (double)(dia - off);
    }
    __syncthreads();
    if (threadIdx.x == 0) {
        double tt = 0.0;
        #pragma unroll
        for (int w = 0; w < 8; ++w) tt += s_c[w];
        atomicAdd(&g_acc, tt);
    }
}

// ---------------------------------------------------------------------------
// Persistent main kernel: 4 CTAs/SM x 128 threads, tile 128(M) x 64(N).
// Wave-keyed startup stagger (same-SM CTAs = bid mod 148, distinguished by
// bid/148) decorrelates tensor-phase vs MUFU-phase across co-resident CTAs.
// Epilogue: v = rsqrt(acc+norms), ex = exp2(-v); two independent sums.
// ---------------------------------------------------------------------------
#define SM_A     0
#define SM_B     32768     // A: 128 rows * 256B
#define SM_NE    49152     // 2 x 128 f (double buffered)
#define SM_NA    50176     // 2 x 64 f
#define SM_RED   50688     // 8 f (4 V + 4 E)
#define SM_CTR   50720     // 1 u32
#define SM_BYTES 50752

static __device__ __forceinline__ void prefetch_tile(uint32_t sb, int tid, int buf,
                                                     int mG, int nG) {
    #pragma unroll
    for (int it = 0; it < 16; ++it) {            // A: 2048 16B chunks
        int idx = it * 128 + tid;
        int row = idx >> 4, cc = idx & 15;
        uint32_t sw = (uint32_t)((cc ^ (row & 7)) << 4);
        cp_async16(sb + SM_A + row * 256 + sw, g_ebf + (size_t)(mG + row) * D + cc * 8);
    }
    #pragma unroll
    for (int it = 0; it < 8; ++it) {             // B: 1024 16B chunks
        int idx = it * 128 + tid;
        int row = idx >> 4, cc = idx & 15;
        uint32_t sw = (uint32_t)((cc ^ (row & 7)) << 4);
        cp_async16(sb + SM_B + row * 256 + sw, g_cbf + (size_t)(nG + row) * D + cc * 8);
    }
    if (tid < 32) {
        cp_async16(sb + SM_NE + buf * 512 + tid * 16, g_ne4 + mG + tid * 4);
    } else if (tid < 48) {
        int l = tid - 32;
        cp_async16(sb + SM_NA + buf * 256 + l * 16, g_nb4 + nG + l * 4);
    }
    CP_COMMIT();
}

__global__ __launch_bounds__(128, 4) void loss_main_kernel(float* __restrict__ out) {
    extern __shared__ __align__(16) uint8_t smem[];
    const uint32_t sb = smem_u32(smem);
    float* s_red = reinterpret_cast<float*>(smem + SM_RED);
    unsigned int* s_ctr = reinterpret_cast<unsigned int*>(smem + SM_CTR);

    const int tid  = threadIdx.x;
    const int wid  = tid >> 5;            // 0..3 = M strip of 32
    const int lane = tid & 31;

    // startup stagger keyed by wave = bid/148: same-SM CTAs (equal bid%148)
    // get distinct delays of ~0/2k/4k/6k cyc over an ~8k-cyc tile period.
    {
        int iters = (int)(blockIdx.x / 148) * 512;
        float d = 1.0f;
        for (int k = 0; k < iters; ++k) d = fmaf(d, 1.0000001f, 1e-30f);
        asm volatile("" :: "f"(d));
    }

    unsigned int cur = blockIdx.x;
    int buf = 0;
    int mG = (int)(cur % MTILES) * 128;
    prefetch_tile(sb, tid, buf, mG, (int)(cur / MTILES) * 64);

    float accV = 0.f, accE = 0.f;         // cross-tile accumulators
    const int r0l = wid * 32 + (lane >> 2);
    const int c0l = 2 * (lane & 3);

    for (;;) {
        if (tid == 0) *s_ctr = atomicAdd(&g_tile, 1u);
        CP_WAIT0();
        __syncthreads();                  // tile + norms + s_ctr visible

        float acc[2][8][4];
        #pragma unroll
        for (int mt = 0; mt < 2; ++mt)
            #pragma unroll
            for (int jn = 0; jn < 8; ++jn)
                #pragma unroll
                for (int e = 0; e < 4; ++e) acc[mt][jn][e] = 0.f;

        #pragma unroll
        for (int ks = 0; ks < 8; ++ks) {
            uint32_t a[2][4], b[4][4];
            #pragma unroll
            for (int mt = 0; mt < 2; ++mt) {
                int row = wid * 32 + mt * 16 + (lane & 15);
                int cc  = 2 * ks + (lane >> 4);
                uint32_t ad = sb + SM_A + row * 256 + (uint32_t)((cc ^ (row & 7)) << 4);
                LDSM_X4(a[mt][0], a[mt][1], a[mt][2], a[mt][3], ad);
            }
            #pragma unroll
            for (int j = 0; j < 4; ++j) {
                int row = j * 16 + (lane & 7) + ((lane >> 4) << 3);
                int cc  = 2 * ks + ((lane >> 3) & 1);
                uint32_t bd = sb + SM_B + row * 256 + (uint32_t)((cc ^ (row & 7)) << 4);
                LDSM_X4_T(b[j][0], b[j][1], b[j][2], b[j][3], bd);
            }
            #pragma unroll
            for (int mt = 0; mt < 2; ++mt)
                #pragma unroll
                for (int jn = 0; jn < 8; ++jn)
                    mma16816(acc[mt][jn], a[mt], b[jn >> 1][(jn & 1) * 2], b[jn >> 1][(jn & 1) * 2 + 1]);
        }

        unsigned int nxt = *s_ctr;        // written pre-sync by tid0
        __syncthreads();                  // all warps done reading smem tiles

        if (nxt < NTILE_TOT)
            prefetch_tile(sb, tid, buf ^ 1, (int)(nxt % MTILES) * 128,
                                            (int)(nxt / MTILES) * 64);

        // ---- epilogue: sq = acc + ne + na == (dist/144.2695)^2 ----
        const float* sne = reinterpret_cast<const float*>(smem + SM_NE + buf * 512);
        const float* sna = reinterpret_cast<const float*>(smem + SM_NA + buf * 256);

        float ner[4];
        #pragma unroll
        for (int q = 0; q < 4; ++q) ner[q] = sne[r0l + q * 8];   // q = mt*2+half
        float2 nac[8];
        const float2* sna2 = reinterpret_cast<const float2*>(sna);
        #pragma unroll
        for (int jn = 0; jn < 8; ++jn) nac[jn] = sna2[(c0l + jn * 8) >> 1];

        if (mG + 128 <= N_ENT) {          // fast path (312/313 bands)
            #pragma unroll
            for (int mt = 0; mt < 2; ++mt) {
                #pragma unroll
                for (int half = 0; half < 2; ++half) {
                    const float ne = ner[mt * 2 + half];
                    #pragma unroll
                    for (int jn = 0; jn < 8; ++jn) {
                        float2 na2 = nac[jn];
                        #pragma unroll
                        for (int e = 0; e < 2; ++e) {
                            float sq = acc[mt][jn][half * 2 + e] + ne + (e ? na2.y : na2.x);
                            float v  = rsqrtf(sq);
                            float ex = exp2f(-v);
                            accV += v;
                            accE += ex;
                        }
                    }
                }
            }
        } else {                           // boundary band: pad rows excluded
            #pragma unroll
            for (int mt = 0; mt < 2; ++mt) {
                #pragma unroll
                for (int half = 0; half < 2; ++half) {
                    const bool valid = (mG + r0l + mt * 16 + half * 8) < N_ENT;
                    const float ne = ner[mt * 2 + half];
                    #pragma unroll
                    for (int jn = 0; jn < 8; ++jn) {
                        float2 na2 = nac[jn];
                        #pragma unroll
                        for (int e = 0; e < 2; ++e) {
                            float sq = acc[mt][jn][half * 2 + e] + ne + (e ? na2.y : na2.x);
                            float v  = rsqrtf(sq);
                            float ex = exp2f(-v);
                            if (valid) { accV += v; accE += ex; }
                        }
                    }
                }
            }
        }

        if (nxt >= NTILE_TOT) break;
        buf ^= 1;
        mG = (int)(nxt % MTILES) * 128;
    }

    // ---- once per CTA: reduce + single double atomic ----
    #pragma unroll
    for (int o = 16; o > 0; o >>= 1) {
        accV += __shfl_xor_sync(0xffffffffu, accV, o);
        accE += __shfl_xor_sync(0xffffffffu, accE, o);
    }
    if (lane == 0) { s_red[wid] = accV; s_red[4 + wid] = accE; }
    __syncthreads();
    if (tid == 0) {
        float sv = s_red[0] + s_red[1] + s_red[2] + s_red[3];
        float se = s_red[4] + s_red[5] + s_red[6] + s_red[7];
        atomicAdd(&g_acc, -((double)LN2F * (double)sv + (double)se));
        __threadfence();
        unsigned int d = atomicAdd(&g_done, 1u);
        if (d == GRID_MAIN - 1) {
            double a = *((volatile double*)&g_acc);
            out[0] = (float)(-a / ((double)BATCH * (double)N_ENT));
        }
    }
}

extern "C" void kernel_launch(void* const* d_in, const int* in_sizes, int n_in,
                              void* d_out, int out_size) {
    const int*   pos_h = (const int*)d_in[0];
    const int*   pos_t = (const int*)d_in[1];
    const int*   neg_h = (const int*)d_in[2];
    // d_in[3] = neg_t_batch: unused by the reference math.
    const float* rpos  = (const float*)d_in[4];
    const float* rneg  = (const float*)d_in[5];
    const float* ent   = (const float*)d_in[6];
    // d_in[7] = L1_flag: fixed 0 (Euclidean path).

    cudaFuncSetAttribute(loss_main_kernel,
                         cudaFuncAttributeMaxDynamicSharedMemorySize, SM_BYTES);

    prep_kernel<<<1316, 256>>>(ent, pos_h, neg_h, rpos, rneg);   // 1316*8*4 = 42112 rows
    corr_kernel<<<BATCH / 8, 256>>>(pos_t);
    loss_main_kernel<<<GRID_MAIN, 128, SM_BYTES>>>((float*)d_out);
}